// round 12
// baseline (speedup 1.0000x reference)
#include <cuda_runtime.h>

// Problem constants
#define NN   4
#define CC   256
#define HS   64
#define WS   64
#define PIX  4096
#define COMPC 64
#define MC   100      // K*K*R*R
#define KK2  25
#define HO   128
#define WO   128
#define OPIX 16384
#define BN_EPS 1e-5f

// ---------------- device scratch (no allocation allowed) ----------------
__device__ float g_comp[NN * COMPC * PIX];         // compressed features
__device__ float g_mlog[2][NN * MC * PIX];         // encoder partial logits (ic halves)
__device__ float g_maskp[NN * KK2 * OPIX];         // softmaxed masks, planar [n][k][i][j]
__device__ float g_y   [NN * CC * PIX];            // W_eff @ high
__device__ float g_weff [CC * CC];                 // [o][c]
__device__ float g_wefft[CC * CC];                 // transposed [c][o]
__device__ float g_wcct [CC * COMPC];              // compressor transposed [ic][oc]
__device__ float g_wcet2[576 * 112];               // encoder pre-padded [(ic*9+r)][og*28+oc%25]
__device__ float g_beff[CC];
__device__ float g_sum [CC];
__device__ float g_sumsq[CC];
__device__ float g_scale[CC];
__device__ float g_shift[CC];

// ---------------- K0: fold weights + transposes + zero BN accumulators ----------------
__global__ void k_fold(const float* __restrict__ wb,
                       const float* __restrict__ wc2,
                       const float* __restrict__ bc2,
                       const float* __restrict__ wcc) {
    int o = blockIdx.x;
    int c = threadIdx.x;
    const float* wbo = wb + o * 512;
    float acc = wbo[256 + c];
    for (int m = 0; m < 256; m++)
        acc += wbo[m] * wc2[m * 256 + c];
    g_weff[o * 256 + c] = acc;
    g_wefft[c * 256 + o] = acc;
    if (o < 64) g_wcct[c * 64 + o] = wcc[o * 256 + c];

    __shared__ float red[256];
    red[c] = wbo[c] * bc2[c];
    __syncthreads();
    for (int s = 128; s > 0; s >>= 1) {
        if (c < s) red[c] += red[c + s];
        __syncthreads();
    }
    if (c == 0) g_beff[o] = red[0];
    if (o == 0) { g_sum[c] = 0.f; g_sumsq[c] = 0.f; }
}

// ---------------- K0b: encoder weights -> pre-padded smem layout ----------------
__global__ void k_trans(const float* __restrict__ wce) {
    int b = blockIdx.x;          // 0..575
    int t = threadIdx.x;         // 0..111
    int og = t / 28, o = t % 28;
    float v = 0.f;
    if (o < 25) v = wce[(og * 25 + o) * 576 + b];
    g_wcet2[b * 112 + t] = v;
}

// ---------------- K1: channel compressor 1x1 (256 -> 64) ----------------
__global__ __launch_bounds__(128) void k_compress(const float* __restrict__ hi,
                                                  const float* __restrict__ bcc) {
    int b = blockIdx.x; int n = b >> 6; int h = b & 63;
    int tid = threadIdx.x;
    int w2 = tid & 31; int og = tid >> 5;
    __shared__ float xs[64][64];
    __shared__ __align__(16) float ws[64][68];   // [cl][oc] padded
    float acc0[16], acc1[16];
    #pragma unroll
    for (int o = 0; o < 16; o++) { float bv = bcc[og * 16 + o]; acc0[o] = bv; acc1[o] = bv; }

    for (int cc0 = 0; cc0 < 256; cc0 += 64) {
        for (int idx = tid; idx < 4096; idx += 128) {
            int cl = idx >> 6, w = idx & 63;
            xs[cl][w] = hi[((n * CC + cc0 + cl) * HS + h) * WS + w];
        }
        for (int idx = tid; idx < 4096; idx += 128) {
            int cl = idx >> 6, oc = idx & 63;
            ws[cl][oc] = g_wcct[(cc0 + cl) * 64 + oc];
        }
        __syncthreads();
        for (int cl = 0; cl < 64; cl++) {
            float x0 = xs[cl][w2], x1 = xs[cl][w2 + 32];
            const float4* wr = (const float4*)&ws[cl][og * 16];
            #pragma unroll
            for (int q = 0; q < 4; q++) {
                float4 wv = wr[q];
                acc0[q*4+0] += wv.x * x0;  acc1[q*4+0] += wv.x * x1;
                acc0[q*4+1] += wv.y * x0;  acc1[q*4+1] += wv.y * x1;
                acc0[q*4+2] += wv.z * x0;  acc1[q*4+2] += wv.z * x1;
                acc0[q*4+3] += wv.w * x0;  acc1[q*4+3] += wv.w * x1;
            }
        }
        __syncthreads();
    }
    #pragma unroll
    for (int o = 0; o < 16; o++) {
        int oc = og * 16 + o;
        g_comp[((n * COMPC + oc) * HS + h) * WS + w2]      = acc0[o];
        g_comp[((n * COMPC + oc) * HS + h) * WS + w2 + 32] = acc1[o];
    }
}

// ---------------- K2: content encoder 3x3 (64 -> 100), ic-split across blocks [R8] ----------------
__global__ __launch_bounds__(128) void k_encode(const float* __restrict__ bce) {
    int b = blockIdx.x;
    int half = b >> 8;
    int nh = b & 255;
    int n = nh >> 6; int h = nh & 63;
    int tid = threadIdx.x;
    int w2 = tid & 31; int og = tid >> 5;
    __shared__ float xs[8][3][66];
    __shared__ __align__(16) float ws[72][112];   // [(cl*9+r)][og*28 + o]
    float acc0[25], acc1[25];
    #pragma unroll
    for (int o = 0; o < 25; o++) { acc0[o] = 0.f; acc1[o] = 0.f; }

    int icbase = half * 32;
    for (int cc0 = icbase; cc0 < icbase + 32; cc0 += 8) {
        __syncthreads();
        for (int idx = tid; idx < 8 * 3 * 66; idx += 128) {
            int cl = idx / 198; int rem = idx % 198; int r = rem / 66; int x = rem % 66;
            int gh = h - 1 + r, gw = x - 1;
            float v = 0.f;
            if (gh >= 0 && gh < 64 && gw >= 0 && gw < 64)
                v = g_comp[((n * COMPC + cc0 + cl) * HS + gh) * WS + gw];
            xs[cl][r][x] = v;
        }
        {
            const float4* src = (const float4*)(g_wcet2 + cc0 * 9 * 112);
            float4* dst = (float4*)ws;
            for (int idx = tid; idx < 2016; idx += 128)
                dst[idx] = src[idx];
        }
        __syncthreads();
        for (int cl = 0; cl < 8; cl++) {
            #pragma unroll
            for (int ky = 0; ky < 3; ky++) {
                #pragma unroll
                for (int kx = 0; kx < 3; kx++) {
                    float x0 = xs[cl][ky][w2 + kx];
                    float x1 = xs[cl][ky][w2 + 32 + kx];
                    const float4* wr = (const float4*)&ws[cl * 9 + ky * 3 + kx][og * 28];
                    #pragma unroll
                    for (int q = 0; q < 7; q++) {
                        float4 wv = wr[q];
                        int o = q * 4;
                        acc0[o] += wv.x * x0;  acc1[o] += wv.x * x1;
                        if (o + 1 < 25) { acc0[o+1] += wv.y * x0;  acc1[o+1] += wv.y * x1; }
                        if (o + 2 < 25) { acc0[o+2] += wv.z * x0;  acc1[o+2] += wv.z * x1; }
                        if (o + 3 < 25) { acc0[o+3] += wv.w * x0;  acc1[o+3] += wv.w * x1; }
                    }
                }
            }
        }
    }
    float* dst = g_mlog[half];
    #pragma unroll
    for (int o = 0; o < 25; o++) {
        int oc = og * 25 + o;
        float bv = (half == 0) ? bce[oc] : 0.f;
        dst[((n * MC + oc) * HS + h) * WS + w2]      = acc0[o] + bv;
        dst[((n * MC + oc) * HS + h) * WS + w2 + 32] = acc1[o] + bv;
    }
}

// ---------------- K2.5: y = W_eff @ high, oc-split [R9 version] ----------------
__global__ __launch_bounds__(256) void k_ymix(const float* __restrict__ hi) {
    int b = blockIdx.x;
    int oc_half = b >> 8;
    int n = (b >> 6) & 3;
    int h = b & 63;
    int tid = threadIdx.x;
    int w2 = tid & 31; int og = tid >> 5;  // 8 groups of 16 oc
    __shared__ float xs[32][64];
    __shared__ __align__(16) float ws[32][132];   // [cl][oc 0..127] padded
    float acc0[16], acc1[16];
    #pragma unroll
    for (int o = 0; o < 16; o++) { acc0[o] = 0.f; acc1[o] = 0.f; }

    for (int cc0 = 0; cc0 < 256; cc0 += 32) {
        for (int idx = tid; idx < 2048; idx += 256) {
            int cl = idx >> 6, w = idx & 63;
            xs[cl][w] = hi[((n * CC + cc0 + cl) * HS + h) * WS + w];
        }
        for (int idx = tid; idx < 4096; idx += 256) {
            int cl = idx >> 7, oc = idx & 127;
            ws[cl][oc] = g_wefft[(cc0 + cl) * 256 + oc_half * 128 + oc];
        }
        __syncthreads();
        for (int cl = 0; cl < 32; cl++) {
            float x0 = xs[cl][w2], x1 = xs[cl][w2 + 32];
            const float4* wr = (const float4*)&ws[cl][og * 16];
            #pragma unroll
            for (int q = 0; q < 4; q++) {
                float4 wv = wr[q];
                acc0[q*4+0] += wv.x * x0;  acc1[q*4+0] += wv.x * x1;
                acc0[q*4+1] += wv.y * x0;  acc1[q*4+1] += wv.y * x1;
                acc0[q*4+2] += wv.z * x0;  acc1[q*4+2] += wv.z * x1;
                acc0[q*4+3] += wv.w * x0;  acc1[q*4+3] += wv.w * x1;
            }
        }
        __syncthreads();
    }
    #pragma unroll
    for (int o = 0; o < 16; o++) {
        int oc = oc_half * 128 + og * 16 + o;
        g_y[((n * CC + oc) * HS + h) * WS + w2]      = acc0[o];
        g_y[((n * CC + oc) * HS + h) * WS + w2 + 32] = acc1[o];
    }
}

// ---------------- K3: pixel-shuffle + softmax over 25 -> planar masks ----------------
// grid 256 = (n,h); 256 threads = qhi(2: output row) x j(128: output col)
__global__ void k_softmax() {
    int b = blockIdx.x; int n = b >> 6; int h = b & 63;
    int qhi = threadIdx.x >> 7;          // ry
    int j   = threadIdx.x & 127;
    int w = j >> 1;
    int q = (qhi << 1) | (j & 1);        // ry*2 + rx
    size_t off = (size_t)n * MC * PIX + h * WS + w;
    const float* base0 = g_mlog[0] + off;
    const float* base1 = g_mlog[1] + off;
    float v[25];
    float mx = -1e30f;
    #pragma unroll
    for (int k = 0; k < 25; k++) {
        int idx = (k * 4 + q) * PIX;
        v[k] = base0[idx] + base1[idx];
        mx = fmaxf(mx, v[k]);
    }
    float s = 0.f;
    #pragma unroll
    for (int k = 0; k < 25; k++) { v[k] = __expf(v[k] - mx); s += v[k]; }
    float inv = 1.f / s;
    int i = 2 * h + qhi;
    float* o = g_maskp + (size_t)n * KK2 * OPIX + i * WO + j;
    #pragma unroll
    for (int k = 0; k < 25; k++) o[k * OPIX] = v[k] * inv;
}

// ---------------- K4: CARAFE + bias + fused BN reduction -> out (pre-BN) ----------------
__global__ __launch_bounds__(256) void k_carafe(float* __restrict__ out) {
    int b = blockIdx.x;
    int n   = b >> 9;
    int h   = (b >> 3) & 63;
    int oc0 = (b & 7) * 32;
    int tid = threadIdx.x;
    int j   = tid & 127;
    int ocg = (tid >> 7) * 16;
    int w   = j >> 1;

    __shared__ float ys[32][5][68];
    for (int idx = tid; idx < 32 * 5 * 68; idx += 256) {
        int oc = idx / 340; int rem = idx % 340; int r = rem / 68; int x = rem % 68;
        int gh = h - 2 + r, gw = x - 2;
        float v = 0.f;
        if (gh >= 0 && gh < 64 && gw >= 0 && gw < 64)
            v = g_y[((n * CC + oc0 + oc) * HS + gh) * WS + gw];
        ys[oc][r][x] = v;
    }
    __syncthreads();

    float m0[25], m1[25];
    {
        const float* mp = g_maskp + (size_t)n * KK2 * OPIX + (2 * h) * WO + j;
        #pragma unroll
        for (int k = 0; k < 25; k++) { m0[k] = mp[k * OPIX]; m1[k] = mp[k * OPIX + WO]; }
    }

    for (int o = 0; o < 16; o++) {
        int oc = ocg + o;
        float a0 = 0.f, a1 = 0.f;
        #pragma unroll
        for (int dy = 0; dy < 5; dy++) {
            #pragma unroll
            for (int dx = 0; dx < 5; dx++) {
                float yv = ys[oc][dy][w + dx];
                a0 += m0[dy * 5 + dx] * yv;
                a1 += m1[dy * 5 + dx] * yv;
            }
        }
        float be = g_beff[oc0 + oc];
        float v0 = a0 + be, v1 = a1 + be;
        size_t co = (size_t)(n * CC + oc0 + oc);
        out[(co * HO + 2 * h)     * WO + j] = v0;
        out[(co * HO + 2 * h + 1) * WO + j] = v1;

        // fused BN partial reduction (all lanes of a warp share oc)
        float s  = v0 + v1;
        float ss = v0 * v0 + v1 * v1;
        #pragma unroll
        for (int off = 16; off > 0; off >>= 1) {
            s  += __shfl_down_sync(0xffffffffu, s, off);
            ss += __shfl_down_sync(0xffffffffu, ss, off);
        }
        if ((tid & 31) == 0) {
            atomicAdd(&g_sum[oc0 + oc], s);
            atomicAdd(&g_sumsq[oc0 + oc], ss);
        }
    }
}

// ---------------- K5b: BN scale/shift ----------------
__global__ void k_bnparam(const float* __restrict__ gamma, const float* __restrict__ beta) {
    int o = threadIdx.x;
    float cnt = (float)(NN * HO * WO);
    float mean = g_sum[o] / cnt;
    float var  = g_sumsq[o] / cnt - mean * mean;
    float sc   = gamma[o] * rsqrtf(var + BN_EPS);
    g_scale[o] = sc;
    g_shift[o] = beta[o] - mean * sc;
}

// ---------------- K6: normalize + affine + ReLU in-place (float4) ----------------
__global__ void k_bnapply(float* __restrict__ x) {
    int idx = blockIdx.x * 256 + threadIdx.x;
    int o = (idx >> 12) & 255;
    float4 v = reinterpret_cast<float4*>(x)[idx];
    float sc = g_scale[o], sh = g_shift[o];
    v.x = fmaxf(v.x * sc + sh, 0.f);
    v.y = fmaxf(v.y * sc + sh, 0.f);
    v.z = fmaxf(v.z * sc + sh, 0.f);
    v.w = fmaxf(v.w * sc + sh, 0.f);
    reinterpret_cast<float4*>(x)[idx] = v;
}

// ---------------- launcher ----------------
extern "C" void kernel_launch(void* const* d_in, const int* in_sizes, int n_in,
                              void* d_out, int out_size) {
    const float* high  = (const float*)d_in[1];
    const float* wcc   = (const float*)d_in[2];
    const float* bcc   = (const float*)d_in[3];
    const float* wce   = (const float*)d_in[4];
    const float* bce   = (const float*)d_in[5];
    const float* wc2   = (const float*)d_in[6];
    const float* bc2   = (const float*)d_in[7];
    const float* wb    = (const float*)d_in[8];
    const float* gamma = (const float*)d_in[9];
    const float* beta  = (const float*)d_in[10];
    float* out = (float*)d_out;

    k_fold    <<<256, 256>>>(wb, wc2, bc2, wcc);
    k_trans   <<<576, 112>>>(wce);
    k_compress<<<256, 128>>>(high, bcc);
    k_encode  <<<512, 128>>>(bce);
    k_ymix    <<<512, 256>>>(high);
    k_softmax <<<256, 256>>>();
    k_carafe  <<<2048, 256>>>(out);
    k_bnparam <<<1, 256>>>(gamma, beta);
    k_bnapply <<<16384, 256>>>(out);
}

// round 14
// speedup vs baseline: 1.0596x; 1.0596x over previous
#include <cuda_runtime.h>

// Problem constants
#define NN   4
#define CC   256
#define HS   64
#define WS   64
#define PIX  4096
#define COMPC 64
#define MC   100      // K*K*R*R
#define KK2  25
#define HO   128
#define WO   128
#define OPIX 16384
#define BN_EPS 1e-5f

// ---------------- device scratch (no allocation allowed) ----------------
__device__ float g_comp[NN * COMPC * PIX];         // compressed features
__device__ float g_mlog[2][NN * MC * PIX];         // encoder partial logits (ic halves)
__device__ float g_maskp[NN * KK2 * OPIX];         // softmaxed masks, planar [n][k][i][j]
__device__ float g_y   [NN * CC * PIX];            // W_eff @ high
__device__ float g_weff [CC * CC];                 // [o][c]
__device__ float g_wefft[CC * CC];                 // transposed [c][o]
__device__ float g_wcct [CC * COMPC];              // compressor transposed [ic][oc]
__device__ float g_wcet2[576 * 112];               // encoder pre-padded [(ic*9+r)][og*28+oc%25]
__device__ float g_beff[CC];
__device__ float g_sum [CC];
__device__ float g_sumsq[CC];
__device__ float g_scale[CC];
__device__ float g_shift[CC];

// ---------------- K0: fold weights + transposes + zero BN accumulators ----------------
__global__ void k_fold(const float* __restrict__ wb,
                       const float* __restrict__ wc2,
                       const float* __restrict__ bc2,
                       const float* __restrict__ wcc) {
    int o = blockIdx.x;
    int c = threadIdx.x;
    const float* wbo = wb + o * 512;
    float acc = wbo[256 + c];
    for (int m = 0; m < 256; m++)
        acc += wbo[m] * wc2[m * 256 + c];
    g_weff[o * 256 + c] = acc;
    g_wefft[c * 256 + o] = acc;
    if (o < 64) g_wcct[c * 64 + o] = wcc[o * 256 + c];

    __shared__ float red[256];
    red[c] = wbo[c] * bc2[c];
    __syncthreads();
    for (int s = 128; s > 0; s >>= 1) {
        if (c < s) red[c] += red[c + s];
        __syncthreads();
    }
    if (c == 0) g_beff[o] = red[0];
    if (o == 0) { g_sum[c] = 0.f; g_sumsq[c] = 0.f; }
}

// ---------------- K0b: encoder weights -> pre-padded smem layout ----------------
__global__ void k_trans(const float* __restrict__ wce) {
    int b = blockIdx.x;          // 0..575
    int t = threadIdx.x;         // 0..111
    int og = t / 28, o = t % 28;
    float v = 0.f;
    if (o < 25) v = wce[(og * 25 + o) * 576 + b];
    g_wcet2[b * 112 + t] = v;
}

// ---------------- K1: channel compressor 1x1 (256 -> 64) ----------------
__global__ __launch_bounds__(128) void k_compress(const float* __restrict__ hi,
                                                  const float* __restrict__ bcc) {
    int b = blockIdx.x; int n = b >> 6; int h = b & 63;
    int tid = threadIdx.x;
    int w2 = tid & 31; int og = tid >> 5;
    __shared__ float xs[64][64];
    __shared__ __align__(16) float ws[64][68];   // [cl][oc] padded
    float acc0[16], acc1[16];
    #pragma unroll
    for (int o = 0; o < 16; o++) { float bv = bcc[og * 16 + o]; acc0[o] = bv; acc1[o] = bv; }

    for (int cc0 = 0; cc0 < 256; cc0 += 64) {
        for (int idx = tid; idx < 4096; idx += 128) {
            int cl = idx >> 6, w = idx & 63;
            xs[cl][w] = hi[((n * CC + cc0 + cl) * HS + h) * WS + w];
        }
        for (int idx = tid; idx < 4096; idx += 128) {
            int cl = idx >> 6, oc = idx & 63;
            ws[cl][oc] = g_wcct[(cc0 + cl) * 64 + oc];
        }
        __syncthreads();
        for (int cl = 0; cl < 64; cl++) {
            float x0 = xs[cl][w2], x1 = xs[cl][w2 + 32];
            const float4* wr = (const float4*)&ws[cl][og * 16];
            #pragma unroll
            for (int q = 0; q < 4; q++) {
                float4 wv = wr[q];
                acc0[q*4+0] += wv.x * x0;  acc1[q*4+0] += wv.x * x1;
                acc0[q*4+1] += wv.y * x0;  acc1[q*4+1] += wv.y * x1;
                acc0[q*4+2] += wv.z * x0;  acc1[q*4+2] += wv.z * x1;
                acc0[q*4+3] += wv.w * x0;  acc1[q*4+3] += wv.w * x1;
            }
        }
        __syncthreads();
    }
    #pragma unroll
    for (int o = 0; o < 16; o++) {
        int oc = og * 16 + o;
        g_comp[((n * COMPC + oc) * HS + h) * WS + w2]      = acc0[o];
        g_comp[((n * COMPC + oc) * HS + h) * WS + w2 + 32] = acc1[o];
    }
}

// ---------------- K2: content encoder 3x3 (64 -> 100), ic-split across blocks [R8] ----------------
__global__ __launch_bounds__(128) void k_encode(const float* __restrict__ bce) {
    int b = blockIdx.x;
    int half = b >> 8;
    int nh = b & 255;
    int n = nh >> 6; int h = nh & 63;
    int tid = threadIdx.x;
    int w2 = tid & 31; int og = tid >> 5;
    __shared__ float xs[8][3][66];
    __shared__ __align__(16) float ws[72][112];   // [(cl*9+r)][og*28 + o]
    float acc0[25], acc1[25];
    #pragma unroll
    for (int o = 0; o < 25; o++) { acc0[o] = 0.f; acc1[o] = 0.f; }

    int icbase = half * 32;
    for (int cc0 = icbase; cc0 < icbase + 32; cc0 += 8) {
        __syncthreads();
        for (int idx = tid; idx < 8 * 3 * 66; idx += 128) {
            int cl = idx / 198; int rem = idx % 198; int r = rem / 66; int x = rem % 66;
            int gh = h - 1 + r, gw = x - 1;
            float v = 0.f;
            if (gh >= 0 && gh < 64 && gw >= 0 && gw < 64)
                v = g_comp[((n * COMPC + cc0 + cl) * HS + gh) * WS + gw];
            xs[cl][r][x] = v;
        }
        {
            const float4* src = (const float4*)(g_wcet2 + cc0 * 9 * 112);
            float4* dst = (float4*)ws;
            for (int idx = tid; idx < 2016; idx += 128)
                dst[idx] = src[idx];
        }
        __syncthreads();
        for (int cl = 0; cl < 8; cl++) {
            #pragma unroll
            for (int ky = 0; ky < 3; ky++) {
                #pragma unroll
                for (int kx = 0; kx < 3; kx++) {
                    float x0 = xs[cl][ky][w2 + kx];
                    float x1 = xs[cl][ky][w2 + 32 + kx];
                    const float4* wr = (const float4*)&ws[cl * 9 + ky * 3 + kx][og * 28];
                    #pragma unroll
                    for (int q = 0; q < 7; q++) {
                        float4 wv = wr[q];
                        int o = q * 4;
                        acc0[o] += wv.x * x0;  acc1[o] += wv.x * x1;
                        if (o + 1 < 25) { acc0[o+1] += wv.y * x0;  acc1[o+1] += wv.y * x1; }
                        if (o + 2 < 25) { acc0[o+2] += wv.z * x0;  acc1[o+2] += wv.z * x1; }
                        if (o + 3 < 25) { acc0[o+3] += wv.w * x0;  acc1[o+3] += wv.w * x1; }
                    }
                }
            }
        }
    }
    float* dst = g_mlog[half];
    #pragma unroll
    for (int o = 0; o < 25; o++) {
        int oc = og * 25 + o;
        float bv = (half == 0) ? bce[oc] : 0.f;
        dst[((n * MC + oc) * HS + h) * WS + w2]      = acc0[o] + bv;
        dst[((n * MC + oc) * HS + h) * WS + w2 + 32] = acc1[o] + bv;
    }
}

// ---------------- K2.5: y = W_eff @ high, oc-split [R9 version] ----------------
__global__ __launch_bounds__(256) void k_ymix(const float* __restrict__ hi) {
    int b = blockIdx.x;
    int oc_half = b >> 8;
    int n = (b >> 6) & 3;
    int h = b & 63;
    int tid = threadIdx.x;
    int w2 = tid & 31; int og = tid >> 5;  // 8 groups of 16 oc
    __shared__ float xs[32][64];
    __shared__ __align__(16) float ws[32][132];   // [cl][oc 0..127] padded
    float acc0[16], acc1[16];
    #pragma unroll
    for (int o = 0; o < 16; o++) { acc0[o] = 0.f; acc1[o] = 0.f; }

    for (int cc0 = 0; cc0 < 256; cc0 += 32) {
        for (int idx = tid; idx < 2048; idx += 256) {
            int cl = idx >> 6, w = idx & 63;
            xs[cl][w] = hi[((n * CC + cc0 + cl) * HS + h) * WS + w];
        }
        for (int idx = tid; idx < 4096; idx += 256) {
            int cl = idx >> 7, oc = idx & 127;
            ws[cl][oc] = g_wefft[(cc0 + cl) * 256 + oc_half * 128 + oc];
        }
        __syncthreads();
        for (int cl = 0; cl < 32; cl++) {
            float x0 = xs[cl][w2], x1 = xs[cl][w2 + 32];
            const float4* wr = (const float4*)&ws[cl][og * 16];
            #pragma unroll
            for (int q = 0; q < 4; q++) {
                float4 wv = wr[q];
                acc0[q*4+0] += wv.x * x0;  acc1[q*4+0] += wv.x * x1;
                acc0[q*4+1] += wv.y * x0;  acc1[q*4+1] += wv.y * x1;
                acc0[q*4+2] += wv.z * x0;  acc1[q*4+2] += wv.z * x1;
                acc0[q*4+3] += wv.w * x0;  acc1[q*4+3] += wv.w * x1;
            }
        }
        __syncthreads();
    }
    #pragma unroll
    for (int o = 0; o < 16; o++) {
        int oc = oc_half * 128 + og * 16 + o;
        g_y[((n * CC + oc) * HS + h) * WS + w2]      = acc0[o];
        g_y[((n * CC + oc) * HS + h) * WS + w2 + 32] = acc1[o];
    }
}

// ---------------- K3: pixel-shuffle + softmax over 25 -> planar masks ----------------
// grid 256 = (n,h); 256 threads = qhi(2: output row) x j(128: output col)
__global__ void k_softmax() {
    int b = blockIdx.x; int n = b >> 6; int h = b & 63;
    int qhi = threadIdx.x >> 7;          // ry
    int j   = threadIdx.x & 127;
    int w = j >> 1;
    int q = (qhi << 1) | (j & 1);        // ry*2 + rx
    size_t off = (size_t)n * MC * PIX + h * WS + w;
    const float* base0 = g_mlog[0] + off;
    const float* base1 = g_mlog[1] + off;
    float v[25];
    float mx = -1e30f;
    #pragma unroll
    for (int k = 0; k < 25; k++) {
        int idx = (k * 4 + q) * PIX;
        v[k] = base0[idx] + base1[idx];
        mx = fmaxf(mx, v[k]);
    }
    float s = 0.f;
    #pragma unroll
    for (int k = 0; k < 25; k++) { v[k] = __expf(v[k] - mx); s += v[k]; }
    float inv = 1.f / s;
    int i = 2 * h + qhi;
    float* o = g_maskp + (size_t)n * KK2 * OPIX + i * WO + j;
    #pragma unroll
    for (int k = 0; k < 25; k++) o[k * OPIX] = v[k] * inv;
}

// ---------------- K4: CARAFE + bias + fused BN reduction (smem-staged) -> out ----------------
__global__ __launch_bounds__(256) void k_carafe(float* __restrict__ out) {
    int b = blockIdx.x;
    int n   = b >> 9;
    int h   = (b >> 3) & 63;
    int oc0 = (b & 7) * 32;
    int tid = threadIdx.x;
    int j   = tid & 127;
    int ocg = (tid >> 7) * 16;
    int w   = j >> 1;
    int wid = tid >> 5;                   // 0..7

    __shared__ float ys[32][5][68];
    __shared__ float redS[8][16], redSS[8][16];
    for (int idx = tid; idx < 32 * 5 * 68; idx += 256) {
        int oc = idx / 340; int rem = idx % 340; int r = rem / 68; int x = rem % 68;
        int gh = h - 2 + r, gw = x - 2;
        float v = 0.f;
        if (gh >= 0 && gh < 64 && gw >= 0 && gw < 64)
            v = g_y[((n * CC + oc0 + oc) * HS + gh) * WS + gw];
        ys[oc][r][x] = v;
    }
    __syncthreads();

    float m0[25], m1[25];
    {
        const float* mp = g_maskp + (size_t)n * KK2 * OPIX + (2 * h) * WO + j;
        #pragma unroll
        for (int k = 0; k < 25; k++) { m0[k] = mp[k * OPIX]; m1[k] = mp[k * OPIX + WO]; }
    }

    for (int o = 0; o < 16; o++) {
        int oc = ocg + o;
        float a0 = 0.f, a1 = 0.f;
        #pragma unroll
        for (int dy = 0; dy < 5; dy++) {
            #pragma unroll
            for (int dx = 0; dx < 5; dx++) {
                float yv = ys[oc][dy][w + dx];
                a0 += m0[dy * 5 + dx] * yv;
                a1 += m1[dy * 5 + dx] * yv;
            }
        }
        float be = g_beff[oc0 + oc];
        float v0 = a0 + be, v1 = a1 + be;
        size_t co = (size_t)(n * CC + oc0 + oc);
        out[(co * HO + 2 * h)     * WO + j] = v0;
        out[(co * HO + 2 * h + 1) * WO + j] = v1;

        // warp-level partials (all lanes of a warp share oc)
        float s  = v0 + v1;
        float ss = v0 * v0 + v1 * v1;
        #pragma unroll
        for (int off = 16; off > 0; off >>= 1) {
            s  += __shfl_down_sync(0xffffffffu, s, off);
            ss += __shfl_down_sync(0xffffffffu, ss, off);
        }
        if ((tid & 31) == 0) { redS[wid][o] = s; redSS[wid][o] = ss; }
    }
    __syncthreads();
    // cross-warp combine: 32 threads, one oc each, 1 atomic pair per oc per block
    if (tid < 32) {
        int wbase = (tid < 16) ? 0 : 4;
        int ol = tid & 15;
        float s  = redS[wbase][ol]  + redS[wbase+1][ol]  + redS[wbase+2][ol]  + redS[wbase+3][ol];
        float ss = redSS[wbase][ol] + redSS[wbase+1][ol] + redSS[wbase+2][ol] + redSS[wbase+3][ol];
        atomicAdd(&g_sum[oc0 + tid], s);
        atomicAdd(&g_sumsq[oc0 + tid], ss);
    }
}

// ---------------- K5b: BN scale/shift ----------------
__global__ void k_bnparam(const float* __restrict__ gamma, const float* __restrict__ beta) {
    int o = threadIdx.x;
    float cnt = (float)(NN * HO * WO);
    float mean = g_sum[o] / cnt;
    float var  = g_sumsq[o] / cnt - mean * mean;
    float sc   = gamma[o] * rsqrtf(var + BN_EPS);
    g_scale[o] = sc;
    g_shift[o] = beta[o] - mean * sc;
}

// ---------------- K6: normalize + affine + ReLU in-place (float4) ----------------
__global__ void k_bnapply(float* __restrict__ x) {
    int idx = blockIdx.x * 256 + threadIdx.x;
    int o = (idx >> 12) & 255;
    float4 v = reinterpret_cast<float4*>(x)[idx];
    float sc = g_scale[o], sh = g_shift[o];
    v.x = fmaxf(v.x * sc + sh, 0.f);
    v.y = fmaxf(v.y * sc + sh, 0.f);
    v.z = fmaxf(v.z * sc + sh, 0.f);
    v.w = fmaxf(v.w * sc + sh, 0.f);
    reinterpret_cast<float4*>(x)[idx] = v;
}

// ---------------- launcher ----------------
extern "C" void kernel_launch(void* const* d_in, const int* in_sizes, int n_in,
                              void* d_out, int out_size) {
    const float* high  = (const float*)d_in[1];
    const float* wcc   = (const float*)d_in[2];
    const float* bcc   = (const float*)d_in[3];
    const float* wce   = (const float*)d_in[4];
    const float* bce   = (const float*)d_in[5];
    const float* wc2   = (const float*)d_in[6];
    const float* bc2   = (const float*)d_in[7];
    const float* wb    = (const float*)d_in[8];
    const float* gamma = (const float*)d_in[9];
    const float* beta  = (const float*)d_in[10];
    float* out = (float*)d_out;

    k_fold    <<<256, 256>>>(wb, wc2, bc2, wcc);
    k_trans   <<<576, 112>>>(wce);
    k_compress<<<256, 128>>>(high, bcc);
    k_encode  <<<512, 128>>>(bce);
    k_ymix    <<<512, 256>>>(high);
    k_softmax <<<256, 256>>>();
    k_carafe  <<<2048, 256>>>(out);
    k_bnparam <<<1, 256>>>(gamma, beta);
    k_bnapply <<<16384, 256>>>(out);
}